// round 1
// baseline (speedup 1.0000x reference)
#include <cuda_runtime.h>
#include <cstdint>

// Problem constants (from reference setup_inputs)
#define T_NODES 80000          // B*N = 16*5000
#define C_DIM   128
#define HF_DIM  128            // H*F = 2*64
#define E_EDGES 1280000
#define NEG_SLOPE 0.2f

// ---------------- static device scratch (no runtime allocation) ----------------
__device__ __align__(16) float g_xl[T_NODES * HF_DIM];   // 40.96 MB
__device__ __align__(16) float g_xr[T_NODES * HF_DIM];   // 40.96 MB
__device__ int g_deg[T_NODES];
__device__ int g_off[T_NODES + 1];
__device__ int g_cur[T_NODES];
__device__ int g_csr_src[E_EDGES];                       // 5.12 MB

// ---------------- f32x2 packed-FMA helpers ----------------
__device__ __forceinline__ unsigned long long pack2(float v) {
    unsigned long long r;
    asm("mov.b64 %0, {%1, %1};" : "=l"(r) : "f"(v));
    return r;
}
__device__ __forceinline__ void fma2(unsigned long long& c, unsigned long long a,
                                     unsigned long long b) {
    asm("fma.rn.f32x2 %0, %1, %2, %3;" : "=l"(c) : "l"(a), "l"(b), "l"(c));
}
__device__ __forceinline__ float2 unpack2(unsigned long long v) {
    float2 f;
    asm("mov.b64 {%0, %1}, %2;" : "=f"(f.x), "=f"(f.y) : "l"(v));
    return f;
}

// ---------------- K1: GEMM  Y[T,128] = X[T,128] @ W[128,128] + b ----------------
// Tile 128x128, 256 threads, 8x8 outputs/thread, packed f32x2 along N.
__global__ void __launch_bounds__(256, 2)
gemm_kernel(const float* __restrict__ X, const float* __restrict__ W,
            const float* __restrict__ bvec, int which) {
    __shared__ float As[32][132];   // [k][row], padded rows (528B, 16B aligned)
    __shared__ float Bs[32][128];   // [k][n]

    float* __restrict__ Y = which ? g_xr : g_xl;

    const int t  = threadIdx.x;
    const int tx = t & 15;          // col group (8 cols each)
    const int ty = t >> 4;          // row group (8 rows each)
    const int rowBase = blockIdx.x * 128;

    unsigned long long acc[8][4] = {};   // 8 rows x 8 cols (as 4 f32x2)

#pragma unroll 1
    for (int kc = 0; kc < 128; kc += 32) {
        // Load A chunk (128 rows x 32 k) transposed into As[k][row]
#pragma unroll
        for (int rr = 0; rr < 4; rr++) {
            int r  = rr * 32 + (t >> 3);
            int kq = (t & 7) * 4;
            float4 v = *(const float4*)&X[(size_t)(rowBase + r) * C_DIM + kc + kq];
            As[kq + 0][r] = v.x;
            As[kq + 1][r] = v.y;
            As[kq + 2][r] = v.z;
            As[kq + 3][r] = v.w;
        }
        // Load B chunk (32 k x 128 n)
#pragma unroll
        for (int q = 0; q < 4; q++) {
            int fidx = q * 256 + t;
            int k  = fidx >> 5;
            int n4 = (fidx & 31) * 4;
            *(float4*)&Bs[k][n4] = *(const float4*)&W[(size_t)(kc + k) * HF_DIM + n4];
        }
        __syncthreads();

#pragma unroll
        for (int k = 0; k < 32; k++) {
            float4 a0 = *(const float4*)&As[k][ty * 8];
            float4 a1 = *(const float4*)&As[k][ty * 8 + 4];
            ulonglong2 b0 = *(const ulonglong2*)&Bs[k][tx * 8];
            ulonglong2 b1 = *(const ulonglong2*)&Bs[k][tx * 8 + 4];
            unsigned long long ap[8];
            ap[0] = pack2(a0.x); ap[1] = pack2(a0.y);
            ap[2] = pack2(a0.z); ap[3] = pack2(a0.w);
            ap[4] = pack2(a1.x); ap[5] = pack2(a1.y);
            ap[6] = pack2(a1.z); ap[7] = pack2(a1.w);
            unsigned long long bb[4] = { b0.x, b0.y, b1.x, b1.y };
#pragma unroll
            for (int i = 0; i < 8; i++)
#pragma unroll
                for (int j = 0; j < 4; j++)
                    fma2(acc[i][j], ap[i], bb[j]);
        }
        __syncthreads();
    }

    // Epilogue: add bias, store
#pragma unroll
    for (int i = 0; i < 8; i++) {
        int row = rowBase + ty * 8 + i;
#pragma unroll
        for (int j = 0; j < 4; j++) {
            float2 c = unpack2(acc[i][j]);
            int col = tx * 8 + j * 2;
            Y[(size_t)row * HF_DIM + col]     = c.x + bvec[col];
            Y[(size_t)row * HF_DIM + col + 1] = c.y + bvec[col + 1];
        }
    }
}

// ---------------- K2: CSR build ----------------
__global__ void zero_deg_kernel() {
    int i = blockIdx.x * blockDim.x + threadIdx.x;
    if (i < T_NODES) g_deg[i] = 0;
}

__global__ void hist_kernel(const int* __restrict__ ei, int E) {
    int e = blockIdx.x * blockDim.x + threadIdx.x;
    if (e < E) {
        int dst = ei[E + e];
        atomicAdd(&g_deg[dst], 1);
    }
}

// single-block exclusive scan over degrees (T=80000, 1024 threads, 79 items/thread)
__global__ void scan_kernel() {
    __shared__ int sums[1024];
    const int t = threadIdx.x;
    const int ITEMS = (T_NODES + 1023) / 1024;   // 79
    int start = t * ITEMS;
    int stop  = start + ITEMS;
    if (stop > T_NODES) stop = T_NODES;
    if (start > T_NODES) start = T_NODES;

    int s = 0;
    for (int i = start; i < stop; i++) s += g_deg[i];
    sums[t] = s;
    __syncthreads();

    // Hillis-Steele inclusive scan
    for (int off = 1; off < 1024; off <<= 1) {
        int v = 0;
        if (t >= off) v = sums[t - off];
        __syncthreads();
        sums[t] += v;
        __syncthreads();
    }

    int run = (t == 0) ? 0 : sums[t - 1];
    for (int i = start; i < stop; i++) {
        g_off[i] = run;
        g_cur[i] = run;
        run += g_deg[i];
    }
    if (t == 1023) g_off[T_NODES] = run;
}

__global__ void scatter_kernel(const int* __restrict__ ei, int E) {
    int e = blockIdx.x * blockDim.x + threadIdx.x;
    if (e < E) {
        int src = ei[e];
        int dst = ei[E + e];
        int pos = atomicAdd(&g_cur[dst], 1);
        g_csr_src[pos] = src;
    }
}

// ---------------- K3: per-dst online softmax + aggregation ----------------
// One warp per dst node. Lane l owns flat features [4l, 4l+4).
// Head = f/64: lanes 0..15 -> head 0, lanes 16..31 -> head 1.
__device__ __forceinline__ float edge_logit(float4 xs, float4 xr, float4 av) {
    float t0 = xs.x + xr.x, t1 = xs.y + xr.y, t2 = xs.z + xr.z, t3 = xs.w + xr.w;
    float l0 = fmaxf(t0, 0.f) + NEG_SLOPE * fminf(t0, 0.f);
    float l1 = fmaxf(t1, 0.f) + NEG_SLOPE * fminf(t1, 0.f);
    float l2 = fmaxf(t2, 0.f) + NEG_SLOPE * fminf(t2, 0.f);
    float l3 = fmaxf(t3, 0.f) + NEG_SLOPE * fminf(t3, 0.f);
    float p = l0 * av.x;
    p = fmaf(l1, av.y, p);
    p = fmaf(l2, av.z, p);
    p = fmaf(l3, av.w, p);
    // reduce over own 16-lane half (one head)
    p += __shfl_xor_sync(0xffffffffu, p, 1);
    p += __shfl_xor_sync(0xffffffffu, p, 2);
    p += __shfl_xor_sync(0xffffffffu, p, 4);
    p += __shfl_xor_sync(0xffffffffu, p, 8);
    return p;
}

__global__ void __launch_bounds__(256)
agg_kernel(const float* __restrict__ att, const float* __restrict__ bias,
           float* __restrict__ out) {
    int warp_id = (blockIdx.x * blockDim.x + threadIdx.x) >> 5;
    int lane = threadIdx.x & 31;
    if (warp_id >= T_NODES) return;
    const int d = warp_id;
    const int fbase = lane * 4;

    const float4* __restrict__ xlp = (const float4*)g_xl;
    const float4* __restrict__ xrp = (const float4*)g_xr;

    float4 av  = *(const float4*)&att[fbase];
    float4 xr  = xrp[(size_t)d * 32 + lane];
    float4 xld = xlp[(size_t)d * 32 + lane];

    // self loop initializes the online softmax state
    float m   = edge_logit(xld, xr, av);
    float den = 1.0f;                 // exp(l_self - m) = 1
    float4 acc = xld;

    int beg = g_off[d], end = g_off[d + 1];

    // software pipeline: src 2-deep, xl 1-deep
    int sB = (beg     < end) ? __ldg(&g_csr_src[beg])     : 0;
    int sC = (beg + 1 < end) ? __ldg(&g_csr_src[beg + 1]) : 0;
    float4 xA = make_float4(0.f, 0.f, 0.f, 0.f);
    if (beg < end) xA = xlp[(size_t)sB * 32 + lane];
    sB = sC;

    for (int e = beg; e < end; e++) {
        // prefetch src for e+2
        sC = (e + 2 < end) ? __ldg(&g_csr_src[e + 2]) : 0;
        // prefetch xl for e+1
        float4 xB = xA;
        if (e + 1 < end) xB = xlp[(size_t)sB * 32 + lane];

        float le = edge_logit(xA, xr, av);
        float nm = fmaxf(m, le);
        float sc = __expf(m - nm);
        float w  = __expf(le - nm);
        den = den * sc + w;
        acc.x = fmaf(w, xA.x, acc.x * sc);
        acc.y = fmaf(w, xA.y, acc.y * sc);
        acc.z = fmaf(w, xA.z, acc.z * sc);
        acc.w = fmaf(w, xA.w, acc.w * sc);
        m = nm;

        xA = xB;
        sB = sC;
    }

    float inv = 1.0f / den;
    float4 bv = *(const float4*)&bias[fbase];
    float4 r;
    r.x = fmaf(acc.x, inv, bv.x);
    r.y = fmaf(acc.y, inv, bv.y);
    r.z = fmaf(acc.z, inv, bv.z);
    r.w = fmaf(acc.w, inv, bv.w);
    ((float4*)out)[(size_t)d * 32 + lane] = r;
}

// ---------------- launch ----------------
extern "C" void kernel_launch(void* const* d_in, const int* in_sizes, int n_in,
                              void* d_out, int out_size) {
    const float* x    = (const float*)d_in[0];
    const int*   ei   = (const int*)d_in[1];
    const float* Wl   = (const float*)d_in[2];
    const float* bl   = (const float*)d_in[3];
    const float* Wr   = (const float*)d_in[4];
    const float* br   = (const float*)d_in[5];
    const float* att  = (const float*)d_in[6];
    const float* bias = (const float*)d_in[7];
    float* out = (float*)d_out;

    const int E = in_sizes[1] / 2;

    // K1: two GEMMs (x @ Wl + bl -> g_xl ; x @ Wr + br -> g_xr)
    gemm_kernel<<<T_NODES / 128, 256>>>(x, Wl, bl, 0);
    gemm_kernel<<<T_NODES / 128, 256>>>(x, Wr, br, 1);

    // K2: CSR over dst
    zero_deg_kernel<<<(T_NODES + 255) / 256, 256>>>();
    hist_kernel<<<(E + 255) / 256, 256>>>(ei, E);
    scan_kernel<<<1, 1024>>>();
    scatter_kernel<<<(E + 255) / 256, 256>>>(ei, E);

    // K3: fused online edge-softmax + aggregation (+ self loops), one warp/node
    agg_kernel<<<(T_NODES * 32 + 255) / 256, 256>>>(att, bias, out);
}

// round 2
// speedup vs baseline: 1.5687x; 1.5687x over previous
#include <cuda_runtime.h>
#include <cstdint>

#define T_NODES 80000          // B*N = 16*5000
#define C_DIM   128
#define HF_DIM  128            // H*F = 2*64
#define E_EDGES 1280000
#define NEG_SLOPE 0.2f
#define SCAN_BLOCKS ((T_NODES + 255) / 256)   // 313

// ---------------- static device scratch ----------------
__device__ __align__(16) float g_xl[T_NODES * HF_DIM];   // 40.96 MB
__device__ __align__(16) float g_xr[T_NODES * HF_DIM];   // 40.96 MB
__device__ int g_deg[T_NODES];
__device__ int g_off[T_NODES + 1];
__device__ int g_cur[T_NODES];
__device__ int g_csr_src[E_EDGES];
__device__ int g_bsum[SCAN_BLOCKS];
__device__ int g_bpre[SCAN_BLOCKS];

// ---------------- f32x2 packed-FMA helpers ----------------
__device__ __forceinline__ unsigned long long pack2(float v) {
    unsigned long long r;
    asm("mov.b64 %0, {%1, %1};" : "=l"(r) : "f"(v));
    return r;
}
__device__ __forceinline__ void fma2(unsigned long long& c, unsigned long long a,
                                     unsigned long long b) {
    asm("fma.rn.f32x2 %0, %1, %2, %3;" : "=l"(c) : "l"(a), "l"(b), "l"(c));
}
__device__ __forceinline__ float2 unpack2(unsigned long long v) {
    float2 f;
    asm("mov.b64 {%0, %1}, %2;" : "=f"(f.x), "=f"(f.y) : "l"(v));
    return f;
}

// ---------------- K1: fused GEMMs  g_xl = X@Wl+bl ; g_xr = X@Wr+br ----------------
// grid (625, 2), 256 threads, 128x128 tile, 8x8/thread via f32x2.
// Also zeroes g_deg (runs before hist).
__global__ void __launch_bounds__(256, 2)
gemm_kernel(const float* __restrict__ X,
            const float* __restrict__ Wl, const float* __restrict__ bl,
            const float* __restrict__ Wr, const float* __restrict__ br) {
    __shared__ float As[32][132];
    __shared__ float Bs[32][128];

    const int which = blockIdx.y;
    const float* __restrict__ W    = which ? Wr : Wl;
    const float* __restrict__ bvec = which ? br : bl;
    float* __restrict__ Y = which ? g_xr : g_xl;

    const int t  = threadIdx.x;
    // zero g_deg across the grid
    {
        int gid = (blockIdx.y * gridDim.x + blockIdx.x) * 256 + t;
        if (gid < T_NODES) g_deg[gid] = 0;
    }

    const int tx = t & 15;
    const int ty = t >> 4;
    const int rowBase = blockIdx.x * 128;

    unsigned long long acc[8][4] = {};

#pragma unroll 1
    for (int kc = 0; kc < 128; kc += 32) {
#pragma unroll
        for (int rr = 0; rr < 4; rr++) {
            int r  = rr * 32 + (t >> 3);
            int kq = (t & 7) * 4;
            float4 v = *(const float4*)&X[(size_t)(rowBase + r) * C_DIM + kc + kq];
            As[kq + 0][r] = v.x;
            As[kq + 1][r] = v.y;
            As[kq + 2][r] = v.z;
            As[kq + 3][r] = v.w;
        }
#pragma unroll
        for (int q = 0; q < 4; q++) {
            int fidx = q * 256 + t;
            int k  = fidx >> 5;
            int n4 = (fidx & 31) * 4;
            *(float4*)&Bs[k][n4] = *(const float4*)&W[(size_t)(kc + k) * HF_DIM + n4];
        }
        __syncthreads();

#pragma unroll
        for (int k = 0; k < 32; k++) {
            float4 a0 = *(const float4*)&As[k][ty * 8];
            float4 a1 = *(const float4*)&As[k][ty * 8 + 4];
            ulonglong2 b0 = *(const ulonglong2*)&Bs[k][tx * 8];
            ulonglong2 b1 = *(const ulonglong2*)&Bs[k][tx * 8 + 4];
            unsigned long long ap[8];
            ap[0] = pack2(a0.x); ap[1] = pack2(a0.y);
            ap[2] = pack2(a0.z); ap[3] = pack2(a0.w);
            ap[4] = pack2(a1.x); ap[5] = pack2(a1.y);
            ap[6] = pack2(a1.z); ap[7] = pack2(a1.w);
            unsigned long long bb[4] = { b0.x, b0.y, b1.x, b1.y };
#pragma unroll
            for (int i = 0; i < 8; i++)
#pragma unroll
                for (int j = 0; j < 4; j++)
                    fma2(acc[i][j], ap[i], bb[j]);
        }
        __syncthreads();
    }

#pragma unroll
    for (int i = 0; i < 8; i++) {
        int row = rowBase + ty * 8 + i;
#pragma unroll
        for (int j = 0; j < 4; j++) {
            float2 c = unpack2(acc[i][j]);
            int col = tx * 8 + j * 2;
            Y[(size_t)row * HF_DIM + col]     = c.x + bvec[col];
            Y[(size_t)row * HF_DIM + col + 1] = c.y + bvec[col + 1];
        }
    }
}

// ---------------- K2: CSR build ----------------
__global__ void hist_kernel(const int* __restrict__ ei, int E) {
    int e = blockIdx.x * blockDim.x + threadIdx.x;
    if (e < E) atomicAdd(&g_deg[ei[E + e]], 1);
}

// partial block sums (313 blocks x 256)
__global__ void bsum_kernel() {
    const int t = threadIdx.x;
    int i = blockIdx.x * 256 + t;
    int v = (i < T_NODES) ? g_deg[i] : 0;
    // warp reduce
    int s = v;
    for (int d = 16; d > 0; d >>= 1) s += __shfl_xor_sync(0xffffffffu, s, d);
    __shared__ int wt[8];
    if ((t & 31) == 0) wt[t >> 5] = s;
    __syncthreads();
    if (t == 0) {
        int tot = 0;
#pragma unroll
        for (int w = 0; w < 8; w++) tot += wt[w];
        g_bsum[blockIdx.x] = tot;
    }
}

// exclusive scan of 313 block sums (1 block, 512 threads)
__global__ void bscan_kernel() {
    __shared__ int s[512];
    const int t = threadIdx.x;
    int v = (t < SCAN_BLOCKS) ? g_bsum[t] : 0;
    s[t] = v;
    __syncthreads();
    for (int off = 1; off < 512; off <<= 1) {
        int y = 0;
        if (t >= off) y = s[t - off];
        __syncthreads();
        s[t] += y;
        __syncthreads();
    }
    if (t < SCAN_BLOCKS) g_bpre[t] = s[t] - v;   // exclusive
}

// per-element offsets (313 blocks x 256)
__global__ void boff_kernel() {
    const int t = threadIdx.x;
    const int lane = t & 31, w = t >> 5;
    int i = blockIdx.x * 256 + t;
    int v = (i < T_NODES) ? g_deg[i] : 0;
    int x = v;
    for (int d = 1; d < 32; d <<= 1) {
        int y = __shfl_up_sync(0xffffffffu, x, d);
        if (lane >= d) x += y;
    }
    __shared__ int wt[8];
    if (lane == 31) wt[w] = x;
    __syncthreads();
    if (t < 8) {
        int y = wt[t];
        for (int d = 1; d < 8; d <<= 1) {
            int z = __shfl_up_sync(0x000000ffu, y, d);
            if (t >= d) y += z;
        }
        wt[t] = y;
    }
    __syncthreads();
    int excl = x - v + (w ? wt[w - 1] : 0);
    int off = g_bpre[blockIdx.x] + excl;
    if (i < T_NODES) {
        g_off[i] = off;
        g_cur[i] = off;
        if (i == T_NODES - 1) g_off[T_NODES] = off + v;
    }
}

__global__ void scatter_kernel(const int* __restrict__ ei, int E) {
    int e = blockIdx.x * blockDim.x + threadIdx.x;
    if (e < E) {
        int src = ei[e];
        int dst = ei[E + e];
        int pos = atomicAdd(&g_cur[dst], 1);
        g_csr_src[pos] = src;
    }
}

// ---------------- K3: per-dst softmax + aggregation (baseline-exp, unroll-2) ----
__device__ __forceinline__ float edge_logit(float4 xs, float4 xr, float4 av) {
    float t0 = xs.x + xr.x, t1 = xs.y + xr.y, t2 = xs.z + xr.z, t3 = xs.w + xr.w;
    float l0 = fmaxf(t0, 0.f) + NEG_SLOPE * fminf(t0, 0.f);
    float l1 = fmaxf(t1, 0.f) + NEG_SLOPE * fminf(t1, 0.f);
    float l2 = fmaxf(t2, 0.f) + NEG_SLOPE * fminf(t2, 0.f);
    float l3 = fmaxf(t3, 0.f) + NEG_SLOPE * fminf(t3, 0.f);
    float p = l0 * av.x;
    p = fmaf(l1, av.y, p);
    p = fmaf(l2, av.z, p);
    p = fmaf(l3, av.w, p);
    p += __shfl_xor_sync(0xffffffffu, p, 1);
    p += __shfl_xor_sync(0xffffffffu, p, 2);
    p += __shfl_xor_sync(0xffffffffu, p, 4);
    p += __shfl_xor_sync(0xffffffffu, p, 8);
    return p;
}

__global__ void __launch_bounds__(256)
agg_kernel(const float* __restrict__ att, const float* __restrict__ bias,
           float* __restrict__ out) {
    int warp_id = (blockIdx.x * blockDim.x + threadIdx.x) >> 5;
    int lane = threadIdx.x & 31;
    if (warp_id >= T_NODES) return;
    const int d = warp_id;
    const int fbase = lane * 4;

    const float4* __restrict__ xlp = (const float4*)g_xl;
    const float4* __restrict__ xrp = (const float4*)g_xr;

    float4 av  = *(const float4*)&att[fbase];
    float4 xr  = xrp[(size_t)d * 32 + lane];
    float4 xld = xlp[(size_t)d * 32 + lane];

    // self-loop logit is the fixed softmax baseline (shift-invariant)
    const float lself = edge_logit(xld, xr, av);
    float den = 1.0f;
    float4 acc = xld;

    const int beg = g_off[d];
    const int n = g_off[d + 1] - beg;

    if (n > 0) {
        const int* __restrict__ sp = g_csr_src + beg;
        const int nm1 = n - 1;
        // pipeline: x loaded 2-deep, src indices 4-deep (clamped)
        int s2 = __ldg(&sp[min(2, nm1)]);
        int s3 = __ldg(&sp[min(3, nm1)]);
        float4 x0 = xlp[(size_t)__ldg(&sp[0]) * 32 + lane];
        float4 x1 = xlp[(size_t)__ldg(&sp[min(1, nm1)]) * 32 + lane];

        for (int i = 0; i < n; i += 2) {
            float4 x2 = xlp[(size_t)s2 * 32 + lane];
            float4 x3 = xlp[(size_t)s3 * 32 + lane];
            int s4 = __ldg(&sp[min(i + 4, nm1)]);
            int s5 = __ldg(&sp[min(i + 5, nm1)]);

            float l0 = edge_logit(x0, xr, av);
            float l1 = edge_logit(x1, xr, av);
            float w0 = __expf(l0 - lself);
            float w1 = (i + 1 < n) ? __expf(l1 - lself) : 0.f;

            den += w0 + w1;
            acc.x = fmaf(w0, x0.x, fmaf(w1, x1.x, acc.x));
            acc.y = fmaf(w0, x0.y, fmaf(w1, x1.y, acc.y));
            acc.z = fmaf(w0, x0.z, fmaf(w1, x1.z, acc.z));
            acc.w = fmaf(w0, x0.w, fmaf(w1, x1.w, acc.w));

            x0 = x2; x1 = x3;
            s2 = s4; s3 = s5;
        }
    }

    float inv = 1.0f / den;
    float4 bv = *(const float4*)&bias[fbase];
    float4 r;
    r.x = fmaf(acc.x, inv, bv.x);
    r.y = fmaf(acc.y, inv, bv.y);
    r.z = fmaf(acc.z, inv, bv.z);
    r.w = fmaf(acc.w, inv, bv.w);
    ((float4*)out)[(size_t)d * 32 + lane] = r;
}

// ---------------- launch ----------------
extern "C" void kernel_launch(void* const* d_in, const int* in_sizes, int n_in,
                              void* d_out, int out_size) {
    const float* x    = (const float*)d_in[0];
    const int*   ei   = (const int*)d_in[1];
    const float* Wl   = (const float*)d_in[2];
    const float* bl   = (const float*)d_in[3];
    const float* Wr   = (const float*)d_in[4];
    const float* br   = (const float*)d_in[5];
    const float* att  = (const float*)d_in[6];
    const float* bias = (const float*)d_in[7];
    float* out = (float*)d_out;

    const int E = in_sizes[1] / 2;

    dim3 ggrid(T_NODES / 128, 2);
    gemm_kernel<<<ggrid, 256>>>(x, Wl, bl, Wr, br);   // also zeroes g_deg

    hist_kernel<<<(E + 255) / 256, 256>>>(ei, E);
    bsum_kernel<<<SCAN_BLOCKS, 256>>>();
    bscan_kernel<<<1, 512>>>();
    boff_kernel<<<SCAN_BLOCKS, 256>>>();
    scatter_kernel<<<(E + 255) / 256, 256>>>(ei, E);

    agg_kernel<<<(T_NODES * 32 + 255) / 256, 256>>>(att, bias, out);
}